// round 4
// baseline (speedup 1.0000x reference)
#include <cuda_runtime.h>
#include <cstdint>

#define N_ENTITIES 100000
#define N_USERS    50000
#define N_FACTORS  4
#define N_RELATIONS 32
#define N_REL_USED 31
#define N_META     8
#define CHANNEL    64
#define N_EDGES    1600000
#define NNZ_CNT    1000000

// ------------------------- device-global scratch ---------------------------
__device__ float g_cnt[N_ENTITIES];
__device__ float g_disen[N_FACTORS * CHANNEL];
__device__ float g_att[N_ENTITIES * N_REL_USED];   // sigmoid(ent[h] . rel[r])

__device__ __forceinline__ void red_add_v4(float* p, float x, float y, float z, float w) {
    asm volatile("red.global.add.v4.f32 [%0], {%1,%2,%3,%4};"
                 :: "l"(p), "f"(x), "f"(y), "f"(z), "f"(w) : "memory");
}

// ---------------------------------------------------------------------------
// 0) zero output accumulators + counts
// ---------------------------------------------------------------------------
__global__ void zero_kernel(float4* __restrict__ out) {
    int i = blockIdx.x * blockDim.x + threadIdx.x;
    const int total4 = (N_ENTITIES + N_USERS) * CHANNEL / 4;
    if (i < total4) out[i] = make_float4(0.f, 0.f, 0.f, 0.f);
    if (i < N_ENTITIES) g_cnt[i] = 0.0f;
}

// ---------------------------------------------------------------------------
// 1) attention table: att[h, r] = sigmoid(dot(ent[h], rel[r]))
//    thread per (h, r); rel transposed in smem for conflict-free LDS
// ---------------------------------------------------------------------------
__global__ void att_table_kernel(const float* __restrict__ ent,
                                 const float* __restrict__ relw) {
    __shared__ float s_relT[CHANNEL * 32];   // [c][r], padded to 32 relations
    for (int i = threadIdx.x; i < CHANNEL * 32; i += blockDim.x) {
        int c = i >> 5, r = i & 31;
        s_relT[i] = (r < N_REL_USED) ? relw[r * CHANNEL + c] : 0.0f;
    }
    __syncthreads();

    int idx = blockIdx.x * blockDim.x + threadIdx.x;
    if (idx >= N_ENTITIES * N_REL_USED) return;
    int h = idx / N_REL_USED;
    int r = idx - h * N_REL_USED;

    const float4* row = (const float4*)&ent[(size_t)h * CHANNEL];
    float d = 0.0f;
    #pragma unroll
    for (int i = 0; i < 16; i++) {
        float4 a = row[i];                       // broadcast within warp (same h)
        d += a.x * s_relT[(i * 4 + 0) * 32 + r]
           + a.y * s_relT[(i * 4 + 1) * 32 + r]
           + a.z * s_relT[(i * 4 + 2) * 32 + r]
           + a.w * s_relT[(i * 4 + 3) * 32 + r];
    }
    g_att[idx] = 1.0f / (1.0f + __expf(-d));
}

// ---------------------------------------------------------------------------
// 2) disen_weight = softmax(disen_weight_att, -1) @ weight   (4 x 64)
// ---------------------------------------------------------------------------
__global__ void disen_kernel(const float* __restrict__ att,
                             const float* __restrict__ weight) {
    int c = threadIdx.x;
    if (c >= CHANNEL) return;
    #pragma unroll
    for (int f = 0; f < N_FACTORS; f++) {
        float a[N_META];
        float m = -1e30f;
        #pragma unroll
        for (int j = 0; j < N_META; j++) { a[j] = att[f * N_META + j]; m = fmaxf(m, a[j]); }
        float s = 0.0f;
        #pragma unroll
        for (int j = 0; j < N_META; j++) { a[j] = __expf(a[j] - m); s += a[j]; }
        float inv = 1.0f / s;
        float acc = 0.0f;
        #pragma unroll
        for (int j = 0; j < N_META; j++) acc += a[j] * inv * weight[j * CHANNEL + c];
        g_disen[f * CHANNEL + c] = acc;
    }
}

// ---------------------------------------------------------------------------
// 3) FUSED scatter: edge aggregation + sparse mm, interleaved 8:5 by warp
//    half-warp (16 lanes x float4) per edge / per nnz
//    800000 edge-pairs : 500000 nnz-pairs -> groups of 13 warps (8 edge, 5 mm)
// ---------------------------------------------------------------------------
#define GROUPS 100000   // 800000/8 == 500000/5
__global__ void fused_scatter_kernel(const float* __restrict__ ent,
                                     const int*   __restrict__ head,
                                     const int*   __restrict__ tail,
                                     const int*   __restrict__ etype,
                                     const int*   __restrict__ mrow,
                                     const int*   __restrict__ mcol,
                                     const float* __restrict__ mval,
                                     const float* __restrict__ relw,
                                     float* __restrict__ out_ent,
                                     float* __restrict__ out_user) {
    __shared__ float s_rel[N_REL_USED * CHANNEL];
    for (int i = threadIdx.x; i < N_REL_USED * CHANNEL; i += blockDim.x)
        s_rel[i] = relw[i];
    __syncthreads();

    int w    = blockIdx.x * 8 + (threadIdx.x >> 5);   // global warp id, < 1.3M
    int lane = threadIdx.x & 31;
    int li   = lane & 15;
    int half = lane >> 4;

    int group = w / 13;
    int r     = w - group * 13;
    if (group >= GROUPS) return;

    if (r < 8) {
        // ---- edge path ----
        int e = (group * 8 + r) * 2 + half;
        int h = head[e];
        int t = tail[e];
        int ri = etype[e] - 1;

        float att  = g_att[h * N_REL_USED + ri];
        float4 rel = *(const float4*)&s_rel[ri * CHANNEL + li * 4];
        float4 et  = *(const float4*)&ent[(size_t)t * CHANNEL + li * 4];

        red_add_v4(&out_ent[(size_t)h * CHANNEL + li * 4],
                   att * et.x * rel.x, att * et.y * rel.y,
                   att * et.z * rel.z, att * et.w * rel.w);
        if (li == 0)
            asm volatile("red.global.add.f32 [%0], %1;"
                         :: "l"(&g_cnt[h]), "f"(1.0f) : "memory");
    } else {
        // ---- spmm path ----
        int i = (group * 5 + (r - 8)) * 2 + half;
        int row = mrow[i];
        int c   = mcol[i];
        float v = mval[i];
        float4 e4 = *(const float4*)&ent[(size_t)c * CHANNEL + li * 4];
        red_add_v4(&out_user[(size_t)row * CHANNEL + li * 4],
                   v * e4.x, v * e4.y, v * e4.z, v * e4.w);
    }
}

// ---------------------------------------------------------------------------
// 4) entity finalize: scatter_mean divide (float4)
// ---------------------------------------------------------------------------
__global__ void entity_final_kernel(float4* __restrict__ out_ent) {
    int i = blockIdx.x * blockDim.x + threadIdx.x;
    if (i >= N_ENTITIES * (CHANNEL / 4)) return;
    float inv = 1.0f / fmaxf(g_cnt[i >> 4], 1.0f);
    float4 v = out_ent[i];
    v.x *= inv; v.y *= inv; v.z *= inv; v.w *= inv;
    out_ent[i] = v;
}

// ---------------------------------------------------------------------------
// 5) user finalize: score softmax + disen blend.  one warp per user
// ---------------------------------------------------------------------------
__global__ void user_final_kernel(const float* __restrict__ user_emb,
                                  const float* __restrict__ latent,
                                  float* __restrict__ out_user) {
    __shared__ float s_lat[N_FACTORS * CHANNEL];
    __shared__ float s_dis[N_FACTORS * CHANNEL];
    for (int i = threadIdx.x; i < N_FACTORS * CHANNEL; i += blockDim.x) {
        s_lat[i] = latent[i];
        s_dis[i] = g_disen[i];
    }
    __syncthreads();

    int u    = blockIdx.x * (blockDim.x >> 5) + (threadIdx.x >> 5);
    int lane = threadIdx.x & 31;
    if (u >= N_USERS) return;

    float2 ue = *(const float2*)&user_emb[(size_t)u * CHANNEL + lane * 2];

    float s[N_FACTORS];
    #pragma unroll
    for (int f = 0; f < N_FACTORS; f++) {
        float p = ue.x * s_lat[f * CHANNEL + lane * 2]
                + ue.y * s_lat[f * CHANNEL + lane * 2 + 1];
        #pragma unroll
        for (int o = 16; o > 0; o >>= 1) p += __shfl_xor_sync(0xFFFFFFFFu, p, o);
        s[f] = p;
    }
    float m = fmaxf(fmaxf(s[0], s[1]), fmaxf(s[2], s[3]));
    float sum = 0.0f;
    #pragma unroll
    for (int f = 0; f < N_FACTORS; f++) { s[f] = __expf(s[f] - m); sum += s[f]; }
    float inv = 1.0f / sum;

    float cx = 0.0f, cy = 0.0f;
    #pragma unroll
    for (int f = 0; f < N_FACTORS; f++) {
        float sc = s[f] * inv;
        cx += sc * s_dis[f * CHANNEL + lane * 2];
        cy += sc * s_dis[f * CHANNEL + lane * 2 + 1];
    }

    float2* p = (float2*)&out_user[(size_t)u * CHANNEL + lane * 2];
    float2 a = *p;
    a.x = a.x * (1.0f + cx);
    a.y = a.y * (1.0f + cy);
    *p = a;
}

// ---------------------------------------------------------------------------
extern "C" void kernel_launch(void* const* d_in, const int* in_sizes, int n_in,
                              void* d_out, int out_size)
{
    const float* entity_emb = (const float*)d_in[0];
    const float* user_emb   = (const float*)d_in[1];
    const float* latent_emb = (const float*)d_in[2];
    const int*   head       = (const int*)d_in[3];
    const int*   tail       = (const int*)d_in[4];
    const int*   edge_type  = (const int*)d_in[5];
    const int*   mat_row    = (const int*)d_in[6];
    const int*   mat_col    = (const int*)d_in[7];
    const float* mat_val    = (const float*)d_in[8];
    const float* rel_w      = (const float*)d_in[9];
    const float* weight     = (const float*)d_in[10];
    const float* disen_att  = (const float*)d_in[11];

    float* out      = (float*)d_out;
    float* out_ent  = out;                                 // (N_ENTITIES, 64)
    float* out_user = out + (size_t)N_ENTITIES * CHANNEL;  // (N_USERS, 64)

    const int total4 = (N_ENTITIES + N_USERS) * CHANNEL / 4;
    zero_kernel<<<(total4 + 255) / 256, 256>>>((float4*)out);
    att_table_kernel<<<(N_ENTITIES * N_REL_USED + 255) / 256, 256>>>(entity_emb, rel_w);
    disen_kernel<<<1, 64>>>(disen_att, weight);

    // 13 warps per group, 100000 groups -> 1.3M warps -> 162500 blocks of 8 warps
    fused_scatter_kernel<<<162500, 256>>>(entity_emb, head, tail, edge_type,
                                          mat_row, mat_col, mat_val, rel_w,
                                          out_ent, out_user);

    entity_final_kernel<<<(N_ENTITIES * (CHANNEL / 4) + 255) / 256, 256>>>((float4*)out_ent);
    user_final_kernel<<<(N_USERS + 7) / 8, 256>>>(user_emb, latent_emb, out_user);
}

// round 5
// speedup vs baseline: 1.3352x; 1.3352x over previous
#include <cuda_runtime.h>
#include <cstdint>

#define N_ENTITIES 100000
#define N_USERS    50000
#define N_FACTORS  4
#define N_RELATIONS 32
#define N_REL_USED 31
#define N_META     8
#define CHANNEL    64
#define N_EDGES    1600000
#define NNZ_CNT    1000000

// persistent-grid split
#define EDGE_BLOCKS 740
#define SPMM_BLOCKS 444
#define TOTAL_BLOCKS (EDGE_BLOCKS + SPMM_BLOCKS)
#define HW_PER_BLOCK 16                     // 256 threads / 16 lanes

// ------------------------- device-global scratch ---------------------------
__device__ float g_cnt[N_ENTITIES];
__device__ float g_disen[N_FACTORS * CHANNEL];
__device__ float g_att[N_ENTITIES * N_REL_USED];   // sigmoid(ent[h] . rel[r])

__device__ __forceinline__ void red_add_v4(float* p, float x, float y, float z, float w) {
    asm volatile("red.global.add.v4.f32 [%0], {%1,%2,%3,%4};"
                 :: "l"(p), "f"(x), "f"(y), "f"(z), "f"(w) : "memory");
}

// ---------------------------------------------------------------------------
// 0) zero output accumulators + counts
// ---------------------------------------------------------------------------
__global__ void zero_kernel(float4* __restrict__ out) {
    int i = blockIdx.x * blockDim.x + threadIdx.x;
    const int total4 = (N_ENTITIES + N_USERS) * CHANNEL / 4;
    if (i < total4) out[i] = make_float4(0.f, 0.f, 0.f, 0.f);
    if (i < N_ENTITIES) g_cnt[i] = 0.0f;
}

// ---------------------------------------------------------------------------
// 1) attention table: att[h, r] = sigmoid(dot(ent[h], rel[r]))
// ---------------------------------------------------------------------------
__global__ void att_table_kernel(const float* __restrict__ ent,
                                 const float* __restrict__ relw) {
    __shared__ float s_relT[CHANNEL * 32];   // [c][r], padded to 32 relations
    for (int i = threadIdx.x; i < CHANNEL * 32; i += blockDim.x) {
        int c = i >> 5, r = i & 31;
        s_relT[i] = (r < N_REL_USED) ? relw[r * CHANNEL + c] : 0.0f;
    }
    __syncthreads();

    int idx = blockIdx.x * blockDim.x + threadIdx.x;
    if (idx >= N_ENTITIES * N_REL_USED) return;
    int h = idx / N_REL_USED;
    int r = idx - h * N_REL_USED;

    const float4* row = (const float4*)&ent[(size_t)h * CHANNEL];
    float d = 0.0f;
    #pragma unroll
    for (int i = 0; i < 16; i++) {
        float4 a = row[i];                       // broadcast within warp (same h)
        d += a.x * s_relT[(i * 4 + 0) * 32 + r]
           + a.y * s_relT[(i * 4 + 1) * 32 + r]
           + a.z * s_relT[(i * 4 + 2) * 32 + r]
           + a.w * s_relT[(i * 4 + 3) * 32 + r];
    }
    g_att[idx] = 1.0f / (1.0f + __expf(-d));
}

// ---------------------------------------------------------------------------
// 2) disen_weight = softmax(disen_weight_att, -1) @ weight   (4 x 64)
// ---------------------------------------------------------------------------
__global__ void disen_kernel(const float* __restrict__ att,
                             const float* __restrict__ weight) {
    int c = threadIdx.x;
    if (c >= CHANNEL) return;
    #pragma unroll
    for (int f = 0; f < N_FACTORS; f++) {
        float a[N_META];
        float m = -1e30f;
        #pragma unroll
        for (int j = 0; j < N_META; j++) { a[j] = att[f * N_META + j]; m = fmaxf(m, a[j]); }
        float s = 0.0f;
        #pragma unroll
        for (int j = 0; j < N_META; j++) { a[j] = __expf(a[j] - m); s += a[j]; }
        float inv = 1.0f / s;
        float acc = 0.0f;
        #pragma unroll
        for (int j = 0; j < N_META; j++) acc += a[j] * inv * weight[j * CHANNEL + c];
        g_disen[f * CHANNEL + c] = acc;
    }
}

// ---------------------------------------------------------------------------
// 3) PERSISTENT fused scatter: block-split edge / spmm, grid-stride loops,
//    half-warp (16 lanes x float4) per item
// ---------------------------------------------------------------------------
__global__ void __launch_bounds__(256)
fused_scatter_kernel(const float* __restrict__ ent,
                     const int*   __restrict__ head,
                     const int*   __restrict__ tail,
                     const int*   __restrict__ etype,
                     const int*   __restrict__ mrow,
                     const int*   __restrict__ mcol,
                     const float* __restrict__ mval,
                     const float* __restrict__ relw,
                     float* __restrict__ out_ent,
                     float* __restrict__ out_user) {
    int li = threadIdx.x & 15;

    if (blockIdx.x < EDGE_BLOCKS) {
        // ---------------- edge path ----------------
        __shared__ float s_rel[N_REL_USED * CHANNEL];
        for (int i = threadIdx.x; i < N_REL_USED * CHANNEL; i += blockDim.x)
            s_rel[i] = relw[i];
        __syncthreads();

        int hw     = blockIdx.x * HW_PER_BLOCK + (threadIdx.x >> 4);
        int stride = EDGE_BLOCKS * HW_PER_BLOCK;

        for (int e = hw; e < N_EDGES; e += stride) {
            int h  = __ldg(&head[e]);
            int t  = __ldg(&tail[e]);
            int ri = __ldg(&etype[e]) - 1;

            float  att = __ldg(&g_att[h * N_REL_USED + ri]);
            float4 rel = *(const float4*)&s_rel[ri * CHANNEL + li * 4];
            float4 et  = __ldg((const float4*)&ent[(size_t)t * CHANNEL + li * 4]);

            red_add_v4(&out_ent[(size_t)h * CHANNEL + li * 4],
                       att * et.x * rel.x, att * et.y * rel.y,
                       att * et.z * rel.z, att * et.w * rel.w);
            if (li == 0)
                asm volatile("red.global.add.f32 [%0], %1;"
                             :: "l"(&g_cnt[h]), "f"(1.0f) : "memory");
        }
    } else {
        // ---------------- spmm path ----------------
        int hw     = (blockIdx.x - EDGE_BLOCKS) * HW_PER_BLOCK + (threadIdx.x >> 4);
        int stride = SPMM_BLOCKS * HW_PER_BLOCK;

        for (int i = hw; i < NNZ_CNT; i += stride) {
            int   r = __ldg(&mrow[i]);
            int   c = __ldg(&mcol[i]);
            float v = __ldg(&mval[i]);
            float4 e4 = __ldg((const float4*)&ent[(size_t)c * CHANNEL + li * 4]);
            red_add_v4(&out_user[(size_t)r * CHANNEL + li * 4],
                       v * e4.x, v * e4.y, v * e4.z, v * e4.w);
        }
    }
}

// ---------------------------------------------------------------------------
// 4) entity finalize: scatter_mean divide (float4)
// ---------------------------------------------------------------------------
__global__ void entity_final_kernel(float4* __restrict__ out_ent) {
    int i = blockIdx.x * blockDim.x + threadIdx.x;
    if (i >= N_ENTITIES * (CHANNEL / 4)) return;
    float inv = 1.0f / fmaxf(g_cnt[i >> 4], 1.0f);
    float4 v = out_ent[i];
    v.x *= inv; v.y *= inv; v.z *= inv; v.w *= inv;
    out_ent[i] = v;
}

// ---------------------------------------------------------------------------
// 5) user finalize: score softmax + disen blend.  one warp per user
// ---------------------------------------------------------------------------
__global__ void user_final_kernel(const float* __restrict__ user_emb,
                                  const float* __restrict__ latent,
                                  float* __restrict__ out_user) {
    __shared__ float s_lat[N_FACTORS * CHANNEL];
    __shared__ float s_dis[N_FACTORS * CHANNEL];
    for (int i = threadIdx.x; i < N_FACTORS * CHANNEL; i += blockDim.x) {
        s_lat[i] = latent[i];
        s_dis[i] = g_disen[i];
    }
    __syncthreads();

    int u    = blockIdx.x * (blockDim.x >> 5) + (threadIdx.x >> 5);
    int lane = threadIdx.x & 31;
    if (u >= N_USERS) return;

    float2 ue = *(const float2*)&user_emb[(size_t)u * CHANNEL + lane * 2];

    float s[N_FACTORS];
    #pragma unroll
    for (int f = 0; f < N_FACTORS; f++) {
        float p = ue.x * s_lat[f * CHANNEL + lane * 2]
                + ue.y * s_lat[f * CHANNEL + lane * 2 + 1];
        #pragma unroll
        for (int o = 16; o > 0; o >>= 1) p += __shfl_xor_sync(0xFFFFFFFFu, p, o);
        s[f] = p;
    }
    float m = fmaxf(fmaxf(s[0], s[1]), fmaxf(s[2], s[3]));
    float sum = 0.0f;
    #pragma unroll
    for (int f = 0; f < N_FACTORS; f++) { s[f] = __expf(s[f] - m); sum += s[f]; }
    float inv = 1.0f / sum;

    float cx = 0.0f, cy = 0.0f;
    #pragma unroll
    for (int f = 0; f < N_FACTORS; f++) {
        float sc = s[f] * inv;
        cx += sc * s_dis[f * CHANNEL + lane * 2];
        cy += sc * s_dis[f * CHANNEL + lane * 2 + 1];
    }

    float2* p = (float2*)&out_user[(size_t)u * CHANNEL + lane * 2];
    float2 a = *p;
    a.x = a.x * (1.0f + cx);
    a.y = a.y * (1.0f + cy);
    *p = a;
}

// ---------------------------------------------------------------------------
extern "C" void kernel_launch(void* const* d_in, const int* in_sizes, int n_in,
                              void* d_out, int out_size)
{
    const float* entity_emb = (const float*)d_in[0];
    const float* user_emb   = (const float*)d_in[1];
    const float* latent_emb = (const float*)d_in[2];
    const int*   head       = (const int*)d_in[3];
    const int*   tail       = (const int*)d_in[4];
    const int*   edge_type  = (const int*)d_in[5];
    const int*   mat_row    = (const int*)d_in[6];
    const int*   mat_col    = (const int*)d_in[7];
    const float* mat_val    = (const float*)d_in[8];
    const float* rel_w      = (const float*)d_in[9];
    const float* weight     = (const float*)d_in[10];
    const float* disen_att  = (const float*)d_in[11];

    float* out      = (float*)d_out;
    float* out_ent  = out;                                 // (N_ENTITIES, 64)
    float* out_user = out + (size_t)N_ENTITIES * CHANNEL;  // (N_USERS, 64)

    const int total4 = (N_ENTITIES + N_USERS) * CHANNEL / 4;
    zero_kernel<<<(total4 + 255) / 256, 256>>>((float4*)out);
    att_table_kernel<<<(N_ENTITIES * N_REL_USED + 255) / 256, 256>>>(entity_emb, rel_w);
    disen_kernel<<<1, 64>>>(disen_att, weight);

    fused_scatter_kernel<<<TOTAL_BLOCKS, 256>>>(entity_emb, head, tail, edge_type,
                                                mat_row, mat_col, mat_val, rel_w,
                                                out_ent, out_user);

    entity_final_kernel<<<(N_ENTITIES * (CHANNEL / 4) + 255) / 256, 256>>>((float4*)out_ent);
    user_final_kernel<<<(N_USERS + 7) / 8, 256>>>(user_emb, latent_emb, out_user);
}

// round 6
// speedup vs baseline: 1.7605x; 1.3186x over previous
#include <cuda_runtime.h>
#include <cstdint>

#define N_ENTITIES 100000
#define N_USERS    50000
#define N_FACTORS  4
#define N_RELATIONS 32
#define N_REL_USED 31
#define N_META     8
#define CHANNEL    64
#define N_EDGES    1600000
#define NNZ_CNT    1000000

// persistent-grid split for the fused scatter
#define EDGE_BLOCKS 740
#define SPMM_BLOCKS 444
#define TOTAL_BLOCKS (EDGE_BLOCKS + SPMM_BLOCKS)
#define HW_PER_BLOCK 16                     // 256 threads / 16 lanes

#define ATT_BLOCKS 1184

// ------------------------- device-global scratch ---------------------------
__device__ float g_cnt[N_ENTITIES];
__device__ float g_disen[N_FACTORS * CHANNEL];
__device__ float g_att[N_ENTITIES * N_REL_USED];   // sigmoid(ent[h] . rel[r])

__device__ __forceinline__ void red_add_v4(float* p, float x, float y, float z, float w) {
    asm volatile("red.global.add.v4.f32 [%0], {%1,%2,%3,%4};"
                 :: "l"(p), "f"(x), "f"(y), "f"(z), "f"(w) : "memory");
}

// ---------------------------------------------------------------------------
// 0) zero output accumulators + counts
// ---------------------------------------------------------------------------
__global__ void zero_kernel(float4* __restrict__ out) {
    int i = blockIdx.x * blockDim.x + threadIdx.x;
    const int total4 = (N_ENTITIES + N_USERS) * CHANNEL / 4;
    if (i < total4) out[i] = make_float4(0.f, 0.f, 0.f, 0.f);
    if (i < N_ENTITIES) g_cnt[i] = 0.0f;
}

// ---------------------------------------------------------------------------
// 1) attention table: att[h, r] = sigmoid(dot(ent[h], rel[r]))
//    WARP per entity, LANE per relation. Persistent grid.
//    rel weights transposed into smem with pitch 33 (conflict-free fill+read).
// ---------------------------------------------------------------------------
#define RELT_PITCH 33
__global__ void __launch_bounds__(256)
att_table_kernel(const float* __restrict__ ent,
                 const float* __restrict__ relw) {
    __shared__ float s_relT[CHANNEL * RELT_PITCH];   // [c][r] padded
    for (int i = threadIdx.x; i < N_REL_USED * CHANNEL; i += blockDim.x) {
        int r = i >> 6;          // i / CHANNEL
        int c = i & 63;          // i % CHANNEL
        s_relT[c * RELT_PITCH + r] = relw[i];        // coalesced LDG, pad STS
    }
    __syncthreads();

    int lane   = threadIdx.x & 31;
    int warp0  = (blockIdx.x * blockDim.x + threadIdx.x) >> 5;
    int nwarps = (ATT_BLOCKS * 256) >> 5;

    for (int h = warp0; h < N_ENTITIES; h += nwarps) {
        const float4* row = (const float4*)&ent[(size_t)h * CHANNEL];
        float d = 0.0f;
        #pragma unroll
        for (int i = 0; i < 16; i++) {
            float4 a = __ldg(&row[i]);               // uniform -> 1-line broadcast
            d += a.x * s_relT[(i * 4 + 0) * RELT_PITCH + lane]
               + a.y * s_relT[(i * 4 + 1) * RELT_PITCH + lane]
               + a.z * s_relT[(i * 4 + 2) * RELT_PITCH + lane]
               + a.w * s_relT[(i * 4 + 3) * RELT_PITCH + lane];
        }
        if (lane < N_REL_USED)
            g_att[h * N_REL_USED + lane] = 1.0f / (1.0f + __expf(-d));
    }
}

// ---------------------------------------------------------------------------
// 2) disen_weight = softmax(disen_weight_att, -1) @ weight   (4 x 64)
// ---------------------------------------------------------------------------
__global__ void disen_kernel(const float* __restrict__ att,
                             const float* __restrict__ weight) {
    int c = threadIdx.x;
    if (c >= CHANNEL) return;
    #pragma unroll
    for (int f = 0; f < N_FACTORS; f++) {
        float a[N_META];
        float m = -1e30f;
        #pragma unroll
        for (int j = 0; j < N_META; j++) { a[j] = att[f * N_META + j]; m = fmaxf(m, a[j]); }
        float s = 0.0f;
        #pragma unroll
        for (int j = 0; j < N_META; j++) { a[j] = __expf(a[j] - m); s += a[j]; }
        float inv = 1.0f / s;
        float acc = 0.0f;
        #pragma unroll
        for (int j = 0; j < N_META; j++) acc += a[j] * inv * weight[j * CHANNEL + c];
        g_disen[f * CHANNEL + c] = acc;
    }
}

// ---------------------------------------------------------------------------
// 3) PERSISTENT fused scatter: block-split edge / spmm, grid-stride loops,
//    half-warp (16 lanes x float4) per item
// ---------------------------------------------------------------------------
__global__ void __launch_bounds__(256)
fused_scatter_kernel(const float* __restrict__ ent,
                     const int*   __restrict__ head,
                     const int*   __restrict__ tail,
                     const int*   __restrict__ etype,
                     const int*   __restrict__ mrow,
                     const int*   __restrict__ mcol,
                     const float* __restrict__ mval,
                     const float* __restrict__ relw,
                     float* __restrict__ out_ent,
                     float* __restrict__ out_user) {
    int li = threadIdx.x & 15;

    if (blockIdx.x < EDGE_BLOCKS) {
        // ---------------- edge path ----------------
        __shared__ float s_rel[N_REL_USED * CHANNEL];
        for (int i = threadIdx.x; i < N_REL_USED * CHANNEL; i += blockDim.x)
            s_rel[i] = relw[i];
        __syncthreads();

        int hw     = blockIdx.x * HW_PER_BLOCK + (threadIdx.x >> 4);
        int stride = EDGE_BLOCKS * HW_PER_BLOCK;

        for (int e = hw; e < N_EDGES; e += stride) {
            int h  = __ldg(&head[e]);
            int t  = __ldg(&tail[e]);
            int ri = __ldg(&etype[e]) - 1;

            float  att = __ldg(&g_att[h * N_REL_USED + ri]);
            float4 rel = *(const float4*)&s_rel[ri * CHANNEL + li * 4];
            float4 et  = __ldg((const float4*)&ent[(size_t)t * CHANNEL + li * 4]);

            red_add_v4(&out_ent[(size_t)h * CHANNEL + li * 4],
                       att * et.x * rel.x, att * et.y * rel.y,
                       att * et.z * rel.z, att * et.w * rel.w);
            if (li == 0)
                asm volatile("red.global.add.f32 [%0], %1;"
                             :: "l"(&g_cnt[h]), "f"(1.0f) : "memory");
        }
    } else {
        // ---------------- spmm path ----------------
        int hw     = (blockIdx.x - EDGE_BLOCKS) * HW_PER_BLOCK + (threadIdx.x >> 4);
        int stride = SPMM_BLOCKS * HW_PER_BLOCK;

        for (int i = hw; i < NNZ_CNT; i += stride) {
            int   r = __ldg(&mrow[i]);
            int   c = __ldg(&mcol[i]);
            float v = __ldg(&mval[i]);
            float4 e4 = __ldg((const float4*)&ent[(size_t)c * CHANNEL + li * 4]);
            red_add_v4(&out_user[(size_t)r * CHANNEL + li * 4],
                       v * e4.x, v * e4.y, v * e4.z, v * e4.w);
        }
    }
}

// ---------------------------------------------------------------------------
// 4) entity finalize: scatter_mean divide (float4)
// ---------------------------------------------------------------------------
__global__ void entity_final_kernel(float4* __restrict__ out_ent) {
    int i = blockIdx.x * blockDim.x + threadIdx.x;
    if (i >= N_ENTITIES * (CHANNEL / 4)) return;
    float inv = 1.0f / fmaxf(g_cnt[i >> 4], 1.0f);
    float4 v = out_ent[i];
    v.x *= inv; v.y *= inv; v.z *= inv; v.w *= inv;
    out_ent[i] = v;
}

// ---------------------------------------------------------------------------
// 5) user finalize: score softmax + disen blend.  one warp per user
// ---------------------------------------------------------------------------
__global__ void user_final_kernel(const float* __restrict__ user_emb,
                                  const float* __restrict__ latent,
                                  float* __restrict__ out_user) {
    __shared__ float s_lat[N_FACTORS * CHANNEL];
    __shared__ float s_dis[N_FACTORS * CHANNEL];
    for (int i = threadIdx.x; i < N_FACTORS * CHANNEL; i += blockDim.x) {
        s_lat[i] = latent[i];
        s_dis[i] = g_disen[i];
    }
    __syncthreads();

    int u    = blockIdx.x * (blockDim.x >> 5) + (threadIdx.x >> 5);
    int lane = threadIdx.x & 31;
    if (u >= N_USERS) return;

    float2 ue = *(const float2*)&user_emb[(size_t)u * CHANNEL + lane * 2];

    float s[N_FACTORS];
    #pragma unroll
    for (int f = 0; f < N_FACTORS; f++) {
        float p = ue.x * s_lat[f * CHANNEL + lane * 2]
                + ue.y * s_lat[f * CHANNEL + lane * 2 + 1];
        #pragma unroll
        for (int o = 16; o > 0; o >>= 1) p += __shfl_xor_sync(0xFFFFFFFFu, p, o);
        s[f] = p;
    }
    float m = fmaxf(fmaxf(s[0], s[1]), fmaxf(s[2], s[3]));
    float sum = 0.0f;
    #pragma unroll
    for (int f = 0; f < N_FACTORS; f++) { s[f] = __expf(s[f] - m); sum += s[f]; }
    float inv = 1.0f / sum;

    float cx = 0.0f, cy = 0.0f;
    #pragma unroll
    for (int f = 0; f < N_FACTORS; f++) {
        float sc = s[f] * inv;
        cx += sc * s_dis[f * CHANNEL + lane * 2];
        cy += sc * s_dis[f * CHANNEL + lane * 2 + 1];
    }

    float2* p = (float2*)&out_user[(size_t)u * CHANNEL + lane * 2];
    float2 a = *p;
    a.x = a.x * (1.0f + cx);
    a.y = a.y * (1.0f + cy);
    *p = a;
}

// ---------------------------------------------------------------------------
extern "C" void kernel_launch(void* const* d_in, const int* in_sizes, int n_in,
                              void* d_out, int out_size)
{
    const float* entity_emb = (const float*)d_in[0];
    const float* user_emb   = (const float*)d_in[1];
    const float* latent_emb = (const float*)d_in[2];
    const int*   head       = (const int*)d_in[3];
    const int*   tail       = (const int*)d_in[4];
    const int*   edge_type  = (const int*)d_in[5];
    const int*   mat_row    = (const int*)d_in[6];
    const int*   mat_col    = (const int*)d_in[7];
    const float* mat_val    = (const float*)d_in[8];
    const float* rel_w      = (const float*)d_in[9];
    const float* weight     = (const float*)d_in[10];
    const float* disen_att  = (const float*)d_in[11];

    float* out      = (float*)d_out;
    float* out_ent  = out;                                 // (N_ENTITIES, 64)
    float* out_user = out + (size_t)N_ENTITIES * CHANNEL;  // (N_USERS, 64)

    const int total4 = (N_ENTITIES + N_USERS) * CHANNEL / 4;
    zero_kernel<<<(total4 + 255) / 256, 256>>>((float4*)out);
    att_table_kernel<<<ATT_BLOCKS, 256>>>(entity_emb, rel_w);
    disen_kernel<<<1, 64>>>(disen_att, weight);

    fused_scatter_kernel<<<TOTAL_BLOCKS, 256>>>(entity_emb, head, tail, edge_type,
                                                mat_row, mat_col, mat_val, rel_w,
                                                out_ent, out_user);

    entity_final_kernel<<<(N_ENTITIES * (CHANNEL / 4) + 255) / 256, 256>>>((float4*)out_ent);
    user_final_kernel<<<(N_USERS + 7) / 8, 256>>>(user_emb, latent_emb, out_user);
}

// round 7
// speedup vs baseline: 1.8407x; 1.0455x over previous
#include <cuda_runtime.h>
#include <cstdint>

#define N_ENTITIES 100000
#define N_USERS    50000
#define N_FACTORS  4
#define N_RELATIONS 32
#define N_REL_USED 31
#define N_META     8
#define CHANNEL    64
#define N_EDGES    1600000
#define NNZ_CNT    1000000

// persistent-grid split for the fused scatter
#define EDGE_BLOCKS 740
#define SPMM_BLOCKS 444
#define TOTAL_BLOCKS (EDGE_BLOCKS + SPMM_BLOCKS)
#define HW_PER_BLOCK 16                     // 256 threads / 16 lanes

// prep kernel split
#define ZERO_BLOCKS 296
#define ATT_BLOCKS  888
#define PREP_BLOCKS (ZERO_BLOCKS + ATT_BLOCKS + 1)   // +1 block for disen

// final kernel split
#define ENTF_BLOCKS 6250     // entity mean: 1.6M float4 / 256
#define USERF_BLOCKS 6250    // users: 50000 / 8 warps
#define FINAL_BLOCKS (ENTF_BLOCKS + USERF_BLOCKS)

// ------------------------- device-global scratch ---------------------------
__device__ float g_cnt[N_ENTITIES];
__device__ float g_disen[N_FACTORS * CHANNEL];
__device__ float g_att[N_ENTITIES * N_REL_USED];   // sigmoid(ent[h] . rel[r])

__device__ __forceinline__ void red_add_v4(float* p, float x, float y, float z, float w) {
    asm volatile("red.global.add.v4.f32 [%0], {%1,%2,%3,%4};"
                 :: "l"(p), "f"(x), "f"(y), "f"(z), "f"(w) : "memory");
}

// ---------------------------------------------------------------------------
// 1) PREP: zero accumulators | att table | disen  (block-split persistent)
// ---------------------------------------------------------------------------
#define RELT_PITCH 33
__global__ void __launch_bounds__(256)
prep_kernel(const float* __restrict__ ent,
            const float* __restrict__ relw,
            const float* __restrict__ datt,
            const float* __restrict__ weight,
            float4* __restrict__ out) {
    int b = blockIdx.x;

    if (b < ZERO_BLOCKS) {
        // ---- zero outputs + counts ----
        const int total4 = (N_ENTITIES + N_USERS) * CHANNEL / 4;
        int i0     = b * 256 + threadIdx.x;
        int stride = ZERO_BLOCKS * 256;
        for (int i = i0; i < total4; i += stride)
            out[i] = make_float4(0.f, 0.f, 0.f, 0.f);
        for (int i = i0; i < N_ENTITIES; i += stride)
            g_cnt[i] = 0.0f;

    } else if (b < ZERO_BLOCKS + ATT_BLOCKS) {
        // ---- attention table: warp per entity, lane per relation ----
        __shared__ float s_relT[CHANNEL * RELT_PITCH];   // [c][r] padded
        for (int i = threadIdx.x; i < N_REL_USED * CHANNEL; i += blockDim.x) {
            int r = i >> 6;
            int c = i & 63;
            s_relT[c * RELT_PITCH + r] = relw[i];        // coalesced LDG, pad STS
        }
        __syncthreads();

        int lane   = threadIdx.x & 31;
        int warp0  = ((b - ZERO_BLOCKS) * 256 + threadIdx.x) >> 5;
        int nwarps = (ATT_BLOCKS * 256) >> 5;

        for (int h = warp0; h < N_ENTITIES; h += nwarps) {
            const float4* row = (const float4*)&ent[(size_t)h * CHANNEL];
            float d = 0.0f;
            #pragma unroll
            for (int i = 0; i < 16; i++) {
                float4 a = __ldg(&row[i]);               // uniform -> broadcast
                d += a.x * s_relT[(i * 4 + 0) * RELT_PITCH + lane]
                   + a.y * s_relT[(i * 4 + 1) * RELT_PITCH + lane]
                   + a.z * s_relT[(i * 4 + 2) * RELT_PITCH + lane]
                   + a.w * s_relT[(i * 4 + 3) * RELT_PITCH + lane];
            }
            if (lane < N_REL_USED)
                g_att[h * N_REL_USED + lane] = 1.0f / (1.0f + __expf(-d));
        }

    } else {
        // ---- disen_weight = softmax(disen_weight_att, -1) @ weight ----
        int c = threadIdx.x;
        if (c >= CHANNEL) return;
        #pragma unroll
        for (int f = 0; f < N_FACTORS; f++) {
            float a[N_META];
            float m = -1e30f;
            #pragma unroll
            for (int j = 0; j < N_META; j++) { a[j] = datt[f * N_META + j]; m = fmaxf(m, a[j]); }
            float s = 0.0f;
            #pragma unroll
            for (int j = 0; j < N_META; j++) { a[j] = __expf(a[j] - m); s += a[j]; }
            float inv = 1.0f / s;
            float acc = 0.0f;
            #pragma unroll
            for (int j = 0; j < N_META; j++) acc += a[j] * inv * weight[j * CHANNEL + c];
            g_disen[f * CHANNEL + c] = acc;
        }
    }
}

// ---------------------------------------------------------------------------
// 2) PERSISTENT fused scatter: block-split edge / spmm, grid-stride loops,
//    half-warp (16 lanes x float4) per item.  At the LTS atomic roofline.
// ---------------------------------------------------------------------------
__global__ void __launch_bounds__(256)
fused_scatter_kernel(const float* __restrict__ ent,
                     const int*   __restrict__ head,
                     const int*   __restrict__ tail,
                     const int*   __restrict__ etype,
                     const int*   __restrict__ mrow,
                     const int*   __restrict__ mcol,
                     const float* __restrict__ mval,
                     const float* __restrict__ relw,
                     float* __restrict__ out_ent,
                     float* __restrict__ out_user) {
    int li = threadIdx.x & 15;

    if (blockIdx.x < EDGE_BLOCKS) {
        // ---------------- edge path ----------------
        __shared__ float s_rel[N_REL_USED * CHANNEL];
        for (int i = threadIdx.x; i < N_REL_USED * CHANNEL; i += blockDim.x)
            s_rel[i] = relw[i];
        __syncthreads();

        int hw     = blockIdx.x * HW_PER_BLOCK + (threadIdx.x >> 4);
        int stride = EDGE_BLOCKS * HW_PER_BLOCK;

        for (int e = hw; e < N_EDGES; e += stride) {
            int h  = __ldg(&head[e]);
            int t  = __ldg(&tail[e]);
            int ri = __ldg(&etype[e]) - 1;

            float  att = __ldg(&g_att[h * N_REL_USED + ri]);
            float4 rel = *(const float4*)&s_rel[ri * CHANNEL + li * 4];
            float4 et  = __ldg((const float4*)&ent[(size_t)t * CHANNEL + li * 4]);

            red_add_v4(&out_ent[(size_t)h * CHANNEL + li * 4],
                       att * et.x * rel.x, att * et.y * rel.y,
                       att * et.z * rel.z, att * et.w * rel.w);
            if (li == 0)
                asm volatile("red.global.add.f32 [%0], %1;"
                             :: "l"(&g_cnt[h]), "f"(1.0f) : "memory");
        }
    } else {
        // ---------------- spmm path ----------------
        int hw     = (blockIdx.x - EDGE_BLOCKS) * HW_PER_BLOCK + (threadIdx.x >> 4);
        int stride = SPMM_BLOCKS * HW_PER_BLOCK;

        for (int i = hw; i < NNZ_CNT; i += stride) {
            int   r = __ldg(&mrow[i]);
            int   c = __ldg(&mcol[i]);
            float v = __ldg(&mval[i]);
            float4 e4 = __ldg((const float4*)&ent[(size_t)c * CHANNEL + li * 4]);
            red_add_v4(&out_user[(size_t)r * CHANNEL + li * 4],
                       v * e4.x, v * e4.y, v * e4.z, v * e4.w);
        }
    }
}

// ---------------------------------------------------------------------------
// 3) FINAL: entity mean-divide | user softmax-blend  (block-split)
// ---------------------------------------------------------------------------
__global__ void __launch_bounds__(256)
final_kernel(const float* __restrict__ user_emb,
             const float* __restrict__ latent,
             float4* __restrict__ out_ent4,
             float* __restrict__ out_user) {
    int b = blockIdx.x;

    if (b < ENTF_BLOCKS) {
        // ---- entity scatter_mean divide ----
        int i = b * 256 + threadIdx.x;
        if (i >= N_ENTITIES * (CHANNEL / 4)) return;
        float inv = 1.0f / fmaxf(g_cnt[i >> 4], 1.0f);
        float4 v = out_ent4[i];
        v.x *= inv; v.y *= inv; v.z *= inv; v.w *= inv;
        out_ent4[i] = v;

    } else {
        // ---- user: score softmax + disen blend, warp per user ----
        __shared__ float s_lat[N_FACTORS * CHANNEL];
        __shared__ float s_dis[N_FACTORS * CHANNEL];
        for (int i = threadIdx.x; i < N_FACTORS * CHANNEL; i += blockDim.x) {
            s_lat[i] = latent[i];
            s_dis[i] = g_disen[i];
        }
        __syncthreads();

        int u    = (b - ENTF_BLOCKS) * 8 + (threadIdx.x >> 5);
        int lane = threadIdx.x & 31;
        if (u >= N_USERS) return;

        float2 ue = *(const float2*)&user_emb[(size_t)u * CHANNEL + lane * 2];

        float s[N_FACTORS];
        #pragma unroll
        for (int f = 0; f < N_FACTORS; f++) {
            float p = ue.x * s_lat[f * CHANNEL + lane * 2]
                    + ue.y * s_lat[f * CHANNEL + lane * 2 + 1];
            #pragma unroll
            for (int o = 16; o > 0; o >>= 1) p += __shfl_xor_sync(0xFFFFFFFFu, p, o);
            s[f] = p;
        }
        float m = fmaxf(fmaxf(s[0], s[1]), fmaxf(s[2], s[3]));
        float sum = 0.0f;
        #pragma unroll
        for (int f = 0; f < N_FACTORS; f++) { s[f] = __expf(s[f] - m); sum += s[f]; }
        float inv = 1.0f / sum;

        float cx = 0.0f, cy = 0.0f;
        #pragma unroll
        for (int f = 0; f < N_FACTORS; f++) {
            float sc = s[f] * inv;
            cx += sc * s_dis[f * CHANNEL + lane * 2];
            cy += sc * s_dis[f * CHANNEL + lane * 2 + 1];
        }

        float2* p = (float2*)&out_user[(size_t)u * CHANNEL + lane * 2];
        float2 a = *p;
        a.x = a.x * (1.0f + cx);
        a.y = a.y * (1.0f + cy);
        *p = a;
    }
}

// ---------------------------------------------------------------------------
extern "C" void kernel_launch(void* const* d_in, const int* in_sizes, int n_in,
                              void* d_out, int out_size)
{
    const float* entity_emb = (const float*)d_in[0];
    const float* user_emb   = (const float*)d_in[1];
    const float* latent_emb = (const float*)d_in[2];
    const int*   head       = (const int*)d_in[3];
    const int*   tail       = (const int*)d_in[4];
    const int*   edge_type  = (const int*)d_in[5];
    const int*   mat_row    = (const int*)d_in[6];
    const int*   mat_col    = (const int*)d_in[7];
    const float* mat_val    = (const float*)d_in[8];
    const float* rel_w      = (const float*)d_in[9];
    const float* weight     = (const float*)d_in[10];
    const float* disen_att  = (const float*)d_in[11];

    float* out      = (float*)d_out;
    float* out_ent  = out;                                 // (N_ENTITIES, 64)
    float* out_user = out + (size_t)N_ENTITIES * CHANNEL;  // (N_USERS, 64)

    prep_kernel<<<PREP_BLOCKS, 256>>>(entity_emb, rel_w, disen_att, weight,
                                      (float4*)out);

    fused_scatter_kernel<<<TOTAL_BLOCKS, 256>>>(entity_emb, head, tail, edge_type,
                                                mat_row, mat_col, mat_val, rel_w,
                                                out_ent, out_user);

    final_kernel<<<FINAL_BLOCKS, 256>>>(user_emb, latent_emb,
                                        (float4*)out_ent, out_user);
}